// round 13
// baseline (speedup 1.0000x reference)
#include <cuda_runtime.h>
#include <math.h>
#include <stdint.h>

// ---------------- problem constants ----------------
#define Bn   128
#define Pn   196
#define ENCn 2048
#define DECn 512
#define Vn   10000
#define Tn   30
#define TMn  29

// ---------------- output layout ----------------
#define OFF_CAPS  0ull
#define OFF_LEN   (128ull*30)
#define OFF_PRED  (OFF_LEN + 128ull)
#define OFF_ALPHA (OFF_PRED + 128ull*29*10000)
#define OFF_ORDER (OFF_ALPHA + 128ull*29*196)

// ---------------- device scratch ----------------
__device__ int      g_order[Bn];
__device__ int      g_lendec[Bn];
__device__ int      g_act[TMn];
__device__ int      g_caps[Bn*Tn];
__device__ int      g_rowmap[Bn*Pn];
__device__ unsigned g_cnt[TMn*8];
__device__ float    g_part[4*128*2048];
__device__ float    g_scratch[29000192];

// scratch offsets (floats)
#define S_ATTENC 0ull            // 25088*512
#define S_MU     12845056ull     // 128*2048
#define S_H      13107200ull     // 128*512
#define S_C      13172736ull     // 128*512
#define S_ALPHA  13238272ull     // 128*196
#define S_X1     13263360ull     // 128*2560
#define S_HOUT   13591040ull     // 128*4608
#define S_WBIG   14180864ull     // 14608*512 (rounded) = [Wfc; Wda; Wfb; Whh]
#define S_WINIT  21660160ull     // 1024*2048 (rounded)
#define S_WIH    23757312ull     // 2048*2560 (rounded copy of W_ih)

__device__ __forceinline__ float sigf(float x) { return 1.0f / (1.0f + expf(-x)); }
__device__ __forceinline__ uint32_t f2tf(float x) {
    uint32_t r; asm("cvt.rna.tf32.f32 %0, %1;" : "=r"(r) : "f"(x)); return r;
}
__device__ __forceinline__ float rndtf(float x) { return __uint_as_float(f2tf(x)); }

// ---------------- sort (stable counting sort, descending lens) + act counts ----------
__global__ void k_sort(const int* __restrict__ lenc, const int* __restrict__ caps,
                       float* __restrict__ out)
{
    __shared__ int so[Bn];
    int tid = threadIdx.x;
    for (int i = tid; i < TMn*8; i += 128) g_cnt[i] = 0;   // reset fused-lstm counters
    if (tid == 0) {
        int idx = 0;
        for (int v = Tn; v >= 2; --v)
            for (int b = 0; b < Bn; ++b)
                if (lenc[b] == v) so[idx++] = b;
    }
    __syncthreads();
    int ob = so[tid];
    g_order[tid]  = ob;
    int L = lenc[ob];
    g_lendec[tid] = L - 1;
    out[OFF_LEN   + tid] = (float)(L - 1);
    out[OFF_ORDER + tid] = (float)ob;
    for (int t = 0; t < Tn; ++t) {
        int cv = caps[ob * Tn + t];
        g_caps[tid * Tn + t] = cv;
        out[OFF_CAPS + (size_t)tid * Tn + t] = (float)cv;
    }
    for (int p = 0; p < Pn; ++p)
        g_rowmap[tid * Pn + p] = ob * Pn + p;
    __syncthreads();
    if (tid < TMn) {
        int cnt = 0;
        for (int b = 0; b < Bn; ++b) cnt += (g_lendec[b] > tid) ? 1 : 0;
        g_act[tid] = cnt;
    }
}

// ---------------- zero masked output regions once ----------------
__global__ void k_zero(float* __restrict__ out)
{
    const size_t n4 = (128ull*29*10000 + 128ull*29*196) / 4;
    float4 z = make_float4(0.f, 0.f, 0.f, 0.f);
    float4* p = (float4*)(out + OFF_PRED);
    for (size_t i = blockIdx.x*(size_t)blockDim.x + threadIdx.x; i < n4;
         i += (size_t)gridDim.x * blockDim.x)
        p[i] = z;
}

// ---------------- pack stacked weights (pre-rounded to tf32) ----------------
__global__ void k_pack(const float* __restrict__ Wfc, const float* __restrict__ Wda,
                       const float* __restrict__ Wfb, const float* __restrict__ Whh,
                       const float* __restrict__ Wih_, const float* __restrict__ Wic,
                       const float* __restrict__ Wih)
{
    float* wb = g_scratch + S_WBIG;
    float* wi = g_scratch + S_WINIT;
    float* wx = g_scratch + S_WIH;
    for (unsigned i = blockIdx.x*256u + threadIdx.x; i < 7479296u; i += gridDim.x*256u) {
        float v;
        if (i < 5120000u)       v = Wfc[i];
        else if (i < 5382144u)  v = Wda[i - 5120000u];
        else if (i < 6430720u)  v = Wfb[i - 5382144u];
        else                    v = Whh[i - 6430720u];
        wb[i] = rndtf(v);
    }
    for (unsigned i = blockIdx.x*256u + threadIdx.x; i < 2097152u; i += gridDim.x*256u)
        wi[i] = rndtf((i < 1048576u) ? Wih_[i] : Wic[i - 1048576u]);
    for (unsigned i = blockIdx.x*256u + threadIdx.x; i < 5242880u; i += gridDim.x*256u)
        wx[i] = rndtf(Wih[i]);
}

// ---------------- mu = mean over P of enc[order[b]] (parallel, float4) ------------
__global__ void k_mu(const float* __restrict__ enc, float* __restrict__ mu)
{
    int b = blockIdx.y;
    int ob = g_order[b];
    int d4 = blockIdx.x * 128 + threadIdx.x;
    const float4* e = (const float4*)(enc + (size_t)ob * Pn * ENCn) + d4;
    float4 s = make_float4(0.f, 0.f, 0.f, 0.f);
#pragma unroll 4
    for (int p = 0; p < Pn; ++p) {
        float4 v = e[(size_t)p * (ENCn/4)];
        s.x += v.x; s.y += v.y; s.z += v.z; s.w += v.w;
    }
    const float r = 1.0f / 196.0f;
    s.x *= r; s.y *= r; s.z *= r; s.w *= r;
    ((float4*)(mu + (size_t)b * ENCn))[d4] = s;
}

// ---------------- tf32 tensor-core GEMM (templated tiles, 256 threads) ------------
// CVT=true: round operands in-kernel. CVT=false: operands pre-rounded (raw loads).
// modes: 0 normal (+bias). 2 merged: col<Vn -> masked preds (+bias), col>=Vn -> hout.
//        3 gates+fused-LSTM: S=4 partials + last-CTA-of-group LSTM
//          (bias = b_ih, C = (float*)b_hh, tstep = t).
#define GBK 32
#define SPAD 36

template<bool CVT>
__device__ __forceinline__ uint32_t ldf(float x) {
    return CVT ? f2tf(x) : __float_as_uint(x);
}

template<int BM, int BN, int WMG, int WNG, int NF, bool CVT>
__global__ void __launch_bounds__(256) k_mma(
    const float* __restrict__ A, const float* __restrict__ B,
    float* __restrict__ C, const float* __restrict__ bias,
    int M, int N, int K, int S, int gatherA, int mode, int tstep,
    const int* __restrict__ actp)
{
    const int ASZf = BM * SPAD;
    const int BSZf = BN * SPAD;
    const int STGf = ASZf + BSZf;
    const int AF4 = BM / 32;
    const int BF4 = BN / 32;

    extern __shared__ float sm[];
    int tid  = threadIdx.x;
    int lane = tid & 31, wid = tid >> 5;
    int wm = wid % WMG, wn = wid / WMG;
    int n0 = blockIdx.x * BN;
    int m0 = blockIdx.y * BM;

    int act = actp ? *actp : M;
    if (m0 >= act) return;

    int Kc = K / S;
    int k0 = blockIdx.z * Kc;
    int nkt = Kc / GBK;

    const float* asrc[AF4]; uint32_t adst[AF4];
#pragma unroll
    for (int q = 0; q < AF4; ++q) {
        int f = tid + q*256;
        int r = f >> 3, kq = f & 7;
        int gr = m0 + r;
        if (gr >= M) gr = M - 1;
        if (gatherA) gr = g_rowmap[gr];
        asrc[q] = A + (size_t)gr * K + k0 + kq*4;
        adst[q] = (r * SPAD + kq*4) * 4;
    }
    const float* bsrc[BF4]; uint32_t bdst[BF4]; int bsz[BF4];
#pragma unroll
    for (int q = 0; q < BF4; ++q) {
        int f = tid + q*256;
        int r = f >> 3, kq = f & 7;
        int gn = n0 + r;
        bsz[q]  = (gn < N) ? 16 : 0;
        bsrc[q] = B + (size_t)(gn < N ? gn : 0) * K + k0 + kq*4;
        bdst[q] = (ASZf + r * SPAD + kq*4) * 4;
    }

    uint32_t smb = (uint32_t)__cvta_generic_to_shared(sm);

    float acc[2][NF][4];
#pragma unroll
    for (int i = 0; i < 2; ++i)
#pragma unroll
        for (int j = 0; j < NF; ++j)
#pragma unroll
            for (int v = 0; v < 4; ++v) acc[i][j][v] = 0.f;

#pragma unroll
    for (int s = 0; s < 3; ++s) {
        if (s < nkt) {
            uint32_t sb = smb + s * STGf * 4;
            int off = s * GBK;
#pragma unroll
            for (int q = 0; q < AF4; ++q)
                asm volatile("cp.async.cg.shared.global [%0], [%1], 16;"
                             :: "r"(sb + adst[q]), "l"(asrc[q] + off));
#pragma unroll
            for (int q = 0; q < BF4; ++q)
                asm volatile("cp.async.cg.shared.global [%0], [%1], 16, %2;"
                             :: "r"(sb + bdst[q]), "l"(bsrc[q] + off), "r"(bsz[q]));
        }
        asm volatile("cp.async.commit_group;");
    }

    int rA = lane >> 2, cA = lane & 3;
    for (int kt = 0; kt < nkt; ++kt) {
        asm volatile("cp.async.wait_group 2;");
        __syncthreads();
        {
            int s = kt + 3;
            if (s < nkt) {
                uint32_t sb = smb + (s & 3) * STGf * 4;
                int off = s * GBK;
#pragma unroll
                for (int q = 0; q < AF4; ++q)
                    asm volatile("cp.async.cg.shared.global [%0], [%1], 16;"
                                 :: "r"(sb + adst[q]), "l"(asrc[q] + off));
#pragma unroll
                for (int q = 0; q < BF4; ++q)
                    asm volatile("cp.async.cg.shared.global [%0], [%1], 16, %2;"
                                 :: "r"(sb + bdst[q]), "l"(bsrc[q] + off), "r"(bsz[q]));
            }
            asm volatile("cp.async.commit_group;");
        }
        const float* Ab = sm + (kt & 3) * STGf;
        const float* Bb = Ab + ASZf;
#pragma unroll
        for (int ka = 0; ka < 4; ++ka) {
            int kk = ka * 8;
            uint32_t a[2][4], b[NF][2];
#pragma unroll
            for (int ma = 0; ma < 2; ++ma) {
                int mb = wm*32 + ma*16;
                a[ma][0] = ldf<CVT>(Ab[(mb + rA    )*SPAD + kk + cA    ]);
                a[ma][1] = ldf<CVT>(Ab[(mb + rA + 8)*SPAD + kk + cA    ]);
                a[ma][2] = ldf<CVT>(Ab[(mb + rA    )*SPAD + kk + cA + 4]);
                a[ma][3] = ldf<CVT>(Ab[(mb + rA + 8)*SPAD + kk + cA + 4]);
            }
#pragma unroll
            for (int na = 0; na < NF; ++na) {
                int nb2 = wn*(NF*8) + na*8;
                b[na][0] = ldf<CVT>(Bb[(nb2 + rA)*SPAD + kk + cA    ]);
                b[na][1] = ldf<CVT>(Bb[(nb2 + rA)*SPAD + kk + cA + 4]);
            }
#pragma unroll
            for (int ma = 0; ma < 2; ++ma)
#pragma unroll
                for (int na = 0; na < NF; ++na)
                    asm volatile(
                        "mma.sync.aligned.m16n8k8.row.col.f32.tf32.tf32.f32 "
                        "{%0,%1,%2,%3},{%4,%5,%6,%7},{%8,%9},{%0,%1,%2,%3};"
                        : "+f"(acc[ma][na][0]), "+f"(acc[ma][na][1]),
                          "+f"(acc[ma][na][2]), "+f"(acc[ma][na][3])
                        : "r"(a[ma][0]), "r"(a[ma][1]), "r"(a[ma][2]), "r"(a[ma][3]),
                          "r"(b[na][0]), "r"(b[na][1]));
        }
    }

    int c2 = (lane & 3) * 2;
    float* hout = g_scratch + S_HOUT;
#pragma unroll
    for (int ma = 0; ma < 2; ++ma) {
#pragma unroll
        for (int na = 0; na < NF; ++na) {
            int row = m0 + wm*32 + ma*16 + rA;
            int col = n0 + wn*(NF*8) + na*8 + c2;
#pragma unroll
            for (int v = 0; v < 4; ++v) {
                int rr = row + (v >> 1) * 8;
                int cc = col + (v & 1);
                if (cc >= N || rr >= M) continue;
                float val = acc[ma][na][v];
                if (S > 1) {
                    g_part[(size_t)blockIdx.z * M * N + (size_t)rr * N + cc] = val;
                } else if (mode == 2) {
                    if (cc < Vn) {
                        if (tstep < g_lendec[rr])
                            C[((size_t)rr * TMn + tstep) * Vn + cc] = val + bias[cc];
                    } else {
                        hout[(size_t)rr * 4608 + (cc - Vn)] = val;
                    }
                } else {
                    if (bias) val += bias[cc];
                    C[(size_t)rr * N + cc] = val;
                }
            }
        }
    }

    // ---- mode 3: fused LSTM — last CTA of the 16-CTA (m-tile, col-group) set ----
    if (mode == 3) {
        __threadfence();            // release: partials visible before counter bump
        __syncthreads();
        __shared__ int lastf;
        int cg = blockIdx.x & 3;    // col-group: n-tiles {cg, 4+cg, 8+cg, 12+cg}
        if (tid == 0) {
            unsigned d = atomicAdd(&g_cnt[tstep*8 + blockIdx.y*4 + cg], 1u);
            lastf = (d == 15u);
        }
        __syncthreads();
        if (lastf) {
            __threadfence();        // acquire side
            const float* bih = bias;
            const float* bhh = C;
            for (int idx = tid; idx < 64*128; idx += 256) {
                int r = idx >> 7;
                int b2 = m0 + r;
                if (!(tstep < g_lendec[b2])) continue;
                int j = cg*128 + (idx & 127);
                float g[4];
#pragma unroll
                for (int q = 0; q < 4; ++q) {
                    int col = q * 512 + j;
                    size_t id2 = (size_t)b2 * 2048 + col;
                    float v = g_part[id2] + g_part[262144 + id2]
                            + g_part[524288 + id2] + g_part[786432 + id2];
                    v += bih[col] + bhh[col] + g_scratch[S_HOUT + (size_t)b2*4608 + 2560 + col];
                    g[q] = v;
                }
                float* hp = g_scratch + S_H + (size_t)b2 * 512;
                float* cp = g_scratch + S_C + (size_t)b2 * 512;
                float cn = sigf(g[1]) * cp[j] + sigf(g[0]) * tanhf(g[2]);
                float hn = sigf(g[3]) * tanhf(cn);
                cp[j] = cn;
                hp[j] = rndtf(hn);
            }
        }
    }
}

// config L (loop): BM=64 BN=128, warps 2x4, warp tile 32x32
#define LBM 64
#define LBN 128
#define LSMEM ((LBM+LBN)*SPAD*4*4)      // 110592
// config G (big): BM=128 BN=128, warps 4x2, warp tile 32x64
#define GBM2 128
#define GBN2 128
#define GSMEM ((GBM2+GBN2)*SPAD*4*4)    // 147456

// ---------------- split-K reduce for init h,c (h stored tf32-rounded) -------------
__global__ void k_inithc(const float* __restrict__ bih_, const float* __restrict__ bic)
{
    int i = blockIdx.x*256 + threadIdx.x;
    int row = i >> 10, col = i & 1023;
    float v = g_part[i] + g_part[131072 + i] + g_part[262144 + i] + g_part[393216 + i];
    if (col < 512) g_scratch[S_H + (size_t)row*512 + col]       = rndtf(v + bih_[col]);
    else           g_scratch[S_C + (size_t)row*512 + col - 512] = v + bic[col - 512];
}

// ---------------- fused attention + weighted context + x1 (512 threads/row) -------
__global__ void __launch_bounds__(512) k_attnwx(
    const float* __restrict__ attenc, const float* __restrict__ bda,
    const float* __restrict__ Watt, const float* __restrict__ enc,
    const float* __restrict__ emb, const float* __restrict__ bfb,
    float* __restrict__ outA, int t)
{
    int b = blockIdx.x;
    if (!(t < g_lendec[b])) return;
    int tid = threadIdx.x, lane = tid & 31, warp = tid >> 5;
    __shared__ __align__(16) float sd[512], sw[512], se[Pn], sa[Pn];
    __shared__ float sred[16];
    __shared__ float smax, ssum;

    const float* hb = g_scratch + S_HOUT + (size_t)b * 4608;
    sd[tid] = hb[tid] + bda[tid];
    sw[tid] = Watt[tid];
    __syncthreads();

    // scores (float4 vectorized)
    for (int p = warp; p < Pn; p += 16) {
        const float4* ae = (const float4*)(attenc + ((size_t)b * Pn + p) * 512);
        const float4* d4 = (const float4*)sd;
        const float4* w4 = (const float4*)sw;
        float s = 0.f;
#pragma unroll
        for (int j = lane; j < 128; j += 32) {
            float4 av = ae[j], dv = d4[j], wv = w4[j];
            s = fmaf(fmaxf(av.x + dv.x, 0.f), wv.x, s);
            s = fmaf(fmaxf(av.y + dv.y, 0.f), wv.y, s);
            s = fmaf(fmaxf(av.z + dv.z, 0.f), wv.z, s);
            s = fmaf(fmaxf(av.w + dv.w, 0.f), wv.w, s);
        }
        for (int o = 16; o; o >>= 1) s += __shfl_xor_sync(0xffffffffu, s, o);
        if (!lane) se[p] = s;
    }
    __syncthreads();

    float v = (tid < Pn) ? se[tid] : -3.0e38f;
    for (int o = 16; o; o >>= 1) v = fmaxf(v, __shfl_xor_sync(0xffffffffu, v, o));
    if (!lane) sred[warp] = v;
    __syncthreads();
    if (tid == 0) {
        float m = sred[0];
        for (int i = 1; i < 16; ++i) m = fmaxf(m, sred[i]);
        smax = m;
    }
    __syncthreads();
    float e = (tid < Pn) ? expf(se[tid] - smax) : 0.f;
    float s2 = e;
    for (int o = 16; o; o >>= 1) s2 += __shfl_xor_sync(0xffffffffu, s2, o);
    if (!lane) sred[warp] = s2;
    __syncthreads();
    if (tid == 0) {
        float s = 0.f;
        for (int i = 0; i < 16; ++i) s += sred[i];
        ssum = s;
    }
    __syncthreads();
    if (tid < Pn) {
        float a = e / ssum;
        sa[tid] = a;
        outA[((size_t)b * TMn + t) * Pn + tid] = a;
    }
    __syncthreads();

    // weighted context * gate -> x1[512..2560) (stored tf32-rounded)
    int ob = g_order[b];
    const float4* ep = (const float4*)(enc + (size_t)ob * Pn * ENCn) + tid;
    float4 s = make_float4(0.f, 0.f, 0.f, 0.f);
#pragma unroll 4
    for (int p = 0; p < Pn; ++p) {
        float4 ev = ep[(size_t)p * (ENCn/4)];
        float av = sa[p];
        s.x = fmaf(ev.x, av, s.x); s.y = fmaf(ev.y, av, s.y);
        s.z = fmaf(ev.z, av, s.z); s.w = fmaf(ev.w, av, s.w);
    }
    float* x1 = g_scratch + S_X1 + (size_t)b * 2560;
    float4 gp = *(const float4*)(hb + 512 + tid*4);
    float4 bb = ((const float4*)bfb)[tid];
    float4 r;
    r.x = rndtf(s.x * sigf(gp.x + bb.x)); r.y = rndtf(s.y * sigf(gp.y + bb.y));
    r.z = rndtf(s.z * sigf(gp.z + bb.z)); r.w = rndtf(s.w * sigf(gp.w + bb.w));
    ((float4*)(x1 + 512))[tid] = r;

    // embedding chunk (rounded)
    if (tid < 128) {
        int cap = g_caps[b * Tn + t];
        float4 ev = ((const float4*)(emb + (size_t)cap * 512))[tid];
        ev.x = rndtf(ev.x); ev.y = rndtf(ev.y); ev.z = rndtf(ev.z); ev.w = rndtf(ev.w);
        ((float4*)x1)[tid] = ev;
    }
}

// ---------------- host ----------------
static inline void gemmL(const float* A, const float* B, float* C, const float* bias,
                         int M, int N, int K, int S, int gather, int mode, int t,
                         const int* actp)
{
    dim3 g((N + LBN - 1) / LBN, (M + LBM - 1) / LBM, S);
    k_mma<LBM, LBN, 2, 4, 4, false><<<g, 256, LSMEM>>>(A, B, C, bias, M, N, K, S, gather, mode, t, actp);
}
static inline void gemmLc(const float* A, const float* B, float* C, const float* bias,
                          int M, int N, int K, int S)
{
    dim3 g((N + LBN - 1) / LBN, (M + LBM - 1) / LBM, S);
    k_mma<LBM, LBN, 2, 4, 4, true><<<g, 256, LSMEM>>>(A, B, C, bias, M, N, K, S, 0, 0, 0, nullptr);
}
static inline void gemmG(const float* A, const float* B, float* C, const float* bias,
                         int M, int N, int K, int gather)
{
    dim3 g((N + GBN2 - 1) / GBN2, (M + GBM2 - 1) / GBM2, 1);
    k_mma<GBM2, GBN2, 4, 2, 8, true><<<g, 256, GSMEM>>>(A, B, C, bias, M, N, K, 1, gather, 0, 0, nullptr);
}

extern "C" void kernel_launch(void* const* d_in, const int* in_sizes, int n_in,
                              void* d_out, int out_size)
{
    const float* enc  = (const float*)d_in[0];
    const int*   caps = (const int*)  d_in[1];
    const int*   lenc = (const int*)  d_in[2];
    const float* emb  = (const float*)d_in[3];
    const float* Wea = (const float*)d_in[4],  *bea = (const float*)d_in[5];
    const float* bda = (const float*)d_in[7];
    const float* Wat = (const float*)d_in[8];
    const float* bih_= (const float*)d_in[11];
    const float* bic = (const float*)d_in[13];
    const float* bih = (const float*)d_in[15];
    const float* bhh = (const float*)d_in[17];
    const float* bfb = (const float*)d_in[19];
    const float* bfc = (const float*)d_in[21];
    float* out = (float*)d_out;

    cudaFuncSetAttribute((const void*)k_mma<LBM, LBN, 2, 4, 4, false>,
                         cudaFuncAttributeMaxDynamicSharedMemorySize, LSMEM);
    cudaFuncSetAttribute((const void*)k_mma<LBM, LBN, 2, 4, 4, true>,
                         cudaFuncAttributeMaxDynamicSharedMemorySize, LSMEM);
    cudaFuncSetAttribute((const void*)k_mma<GBM2, GBN2, 4, 2, 8, true>,
                         cudaFuncAttributeMaxDynamicSharedMemorySize, GSMEM);

    float* S0 = nullptr;
    cudaGetSymbolAddress((void**)&S0, g_scratch);
    int* actd = nullptr;
    cudaGetSymbolAddress((void**)&actd, g_act);
    float* attenc = S0 + S_ATTENC;
    float* mu     = S0 + S_MU;
    float* h      = S0 + S_H;
    float* x1     = S0 + S_X1;
    float* hout   = S0 + S_HOUT;
    float* wbig   = S0 + S_WBIG;
    float* wcombo = S0 + S_WBIG + (size_t)Vn * 512;
    float* winit  = S0 + S_WINIT;
    float* wih    = S0 + S_WIH;

    // init
    k_sort<<<1, 128>>>(lenc, caps, out);
    k_zero<<<592, 256>>>(out);
    k_pack<<<2048, 256>>>((const float*)d_in[20], (const float*)d_in[6],
                          (const float*)d_in[18], (const float*)d_in[16],
                          (const float*)d_in[10], (const float*)d_in[12],
                          (const float*)d_in[14]);
    k_mu<<<dim3(4, 128), 128>>>(enc, mu);
    gemmLc(mu, winit, nullptr, nullptr, 128, 1024, 2048, 4);
    k_inithc<<<512, 256>>>(bih_, bic);
    gemmG(enc, Wea, attenc, bea, Bn * Pn, 512, 2048, 1);
    // prologue hout for t=0 (h pre-rounded, wcombo pre-rounded)
    gemmL(h, wcombo, hout, nullptr, 128, 4608, 512, 1, 0, 0, 0, nullptr);

    // decode loop (3 kernels/step): attnwx -> gates+LSTM -> merged(fc_t + hout_{t+1})
    for (int t = 0; t < TMn; ++t) {
        const int* ap = actd + t;
        k_attnwx<<<128, 512>>>(attenc, bda, Wat, enc, emb, bfb, out + OFF_ALPHA, t);
        gemmL(x1, wih, (float*)bhh, bih, 128, 2048, 2560, 4, 0, 3, t, ap);
        gemmL(h, wbig, out + OFF_PRED, bfc, 128, Vn + 4608, 512, 1, 0, 2, t, ap);
    }
}

// round 14
// speedup vs baseline: 1.2871x; 1.2871x over previous
#include <cuda_runtime.h>
#include <math.h>
#include <stdint.h>

// ---------------- problem constants ----------------
#define Bn   128
#define Pn   196
#define ENCn 2048
#define DECn 512
#define Vn   10000
#define Tn   30
#define TMn  29

// ---------------- output layout ----------------
#define OFF_CAPS  0ull
#define OFF_LEN   (128ull*30)
#define OFF_PRED  (OFF_LEN + 128ull)
#define OFF_ALPHA (OFF_PRED + 128ull*29*10000)
#define OFF_ORDER (OFF_ALPHA + 128ull*29*196)

// ---------------- device scratch ----------------
__device__ int   g_order[Bn];
__device__ int   g_lendec[Bn];
__device__ int   g_act[TMn];
__device__ int   g_caps[Bn*Tn];
__device__ float g_part[4*128*2048];
__device__ float g_scratch[81428992];

// scratch offsets (floats)
#define S_ATTENC 0ull            // 25088*512
#define S_MU     12845056ull     // 128*2048 (tf32-rounded)
#define S_H      13107200ull     // 128*512 (tf32-rounded)
#define S_C      13172736ull     // 128*512
#define S_ALPHA  13238272ull     // 128*196
#define S_X1     13263360ull     // 128*2560 (tf32-rounded)
#define S_HOUT   13591040ull     // 128*4608
#define S_WBIG   14180864ull     // 14608*512 (rounded) = [Wfc; Wda; Wfb; Whh]
#define S_WINIT  21660160ull     // 1024*2048 (rounded)
#define S_WIH    23757312ull     // 2048*2560 (rounded copy of W_ih)
#define S_WEA    29000192ull     // 512*2048 (rounded W_enc_att)
#define S_ENCR   30048768ull     // 25088*2048 (gathered, tf32-rounded enc)

__device__ __forceinline__ float sigf(float x) { return 1.0f / (1.0f + expf(-x)); }
__device__ __forceinline__ uint32_t f2tf(float x) {
    uint32_t r; asm("cvt.rna.tf32.f32 %0, %1;" : "=r"(r) : "f"(x)); return r;
}
__device__ __forceinline__ float rndtf(float x) { return __uint_as_float(f2tf(x)); }

// ---------------- sort (stable counting sort, descending lens) + act counts ----------
__global__ void k_sort(const int* __restrict__ lenc, const int* __restrict__ caps,
                       float* __restrict__ out)
{
    __shared__ int so[Bn];
    int tid = threadIdx.x;
    if (tid == 0) {
        int idx = 0;
        for (int v = Tn; v >= 2; --v)
            for (int b = 0; b < Bn; ++b)
                if (lenc[b] == v) so[idx++] = b;
    }
    __syncthreads();
    int ob = so[tid];
    g_order[tid]  = ob;
    int L = lenc[ob];
    g_lendec[tid] = L - 1;
    out[OFF_LEN   + tid] = (float)(L - 1);
    out[OFF_ORDER + tid] = (float)ob;
    for (int t = 0; t < Tn; ++t) {
        int cv = caps[ob * Tn + t];
        g_caps[tid * Tn + t] = cv;
        out[OFF_CAPS + (size_t)tid * Tn + t] = (float)cv;
    }
    __syncthreads();
    if (tid < TMn) {
        int cnt = 0;
        for (int b = 0; b < Bn; ++b) cnt += (g_lendec[b] > tid) ? 1 : 0;
        g_act[tid] = cnt;
    }
}

// ---------------- zero masked output regions once ----------------
__global__ void k_zero(float* __restrict__ out)
{
    const size_t n4 = (128ull*29*10000 + 128ull*29*196) / 4;
    float4 z = make_float4(0.f, 0.f, 0.f, 0.f);
    float4* p = (float4*)(out + OFF_PRED);
    for (size_t i = blockIdx.x*(size_t)blockDim.x + threadIdx.x; i < n4;
         i += (size_t)gridDim.x * blockDim.x)
        p[i] = z;
}

// ---------------- pack stacked weights (pre-rounded to tf32) ----------------
__global__ void k_pack(const float* __restrict__ Wfc, const float* __restrict__ Wda,
                       const float* __restrict__ Wfb, const float* __restrict__ Whh,
                       const float* __restrict__ Wih_, const float* __restrict__ Wic,
                       const float* __restrict__ Wih, const float* __restrict__ Wea)
{
    float* wb = g_scratch + S_WBIG;
    float* wi = g_scratch + S_WINIT;
    float* wx = g_scratch + S_WIH;
    float* we = g_scratch + S_WEA;
    for (unsigned i = blockIdx.x*256u + threadIdx.x; i < 7479296u; i += gridDim.x*256u) {
        float v;
        if (i < 5120000u)       v = Wfc[i];
        else if (i < 5382144u)  v = Wda[i - 5120000u];
        else if (i < 6430720u)  v = Wfb[i - 5382144u];
        else                    v = Whh[i - 6430720u];
        wb[i] = rndtf(v);
    }
    for (unsigned i = blockIdx.x*256u + threadIdx.x; i < 2097152u; i += gridDim.x*256u)
        wi[i] = rndtf((i < 1048576u) ? Wih_[i] : Wic[i - 1048576u]);
    for (unsigned i = blockIdx.x*256u + threadIdx.x; i < 5242880u; i += gridDim.x*256u)
        wx[i] = rndtf(Wih[i]);
    for (unsigned i = blockIdx.x*256u + threadIdx.x; i < 1048576u; i += gridDim.x*256u)
        we[i] = rndtf(Wea[i]);
}

// ---------------- fused: mu (rounded) + gathered tf32-rounded enc copy ------------
__global__ void k_mucopy(const float* __restrict__ enc, float* __restrict__ mu,
                         float* __restrict__ encr)
{
    int b = blockIdx.y;
    int ob = g_order[b];
    int d4 = blockIdx.x * 128 + threadIdx.x;   // float4 column 0..511
    const float4* e = (const float4*)(enc  + (size_t)ob * Pn * ENCn) + d4;
    float4*       o = (float4*)      (encr + (size_t)b  * Pn * ENCn) + d4;
    float4 s = make_float4(0.f, 0.f, 0.f, 0.f);
#pragma unroll 4
    for (int p = 0; p < Pn; ++p) {
        float4 v = e[(size_t)p * (ENCn/4)];
        s.x += v.x; s.y += v.y; s.z += v.z; s.w += v.w;
        float4 rv;
        rv.x = rndtf(v.x); rv.y = rndtf(v.y); rv.z = rndtf(v.z); rv.w = rndtf(v.w);
        o[(size_t)p * (ENCn/4)] = rv;
    }
    const float r = 1.0f / 196.0f;
    float4 m;
    m.x = rndtf(s.x * r); m.y = rndtf(s.y * r);
    m.z = rndtf(s.z * r); m.w = rndtf(s.w * r);
    ((float4*)(mu + (size_t)b * ENCn))[d4] = m;
}

// ---------------- tf32 tensor-core GEMM (templated tiles, 256 threads) ------------
// All operands pre-rounded to tf32 (raw loads, no CVT in inner loop).
// modes: 0 normal (+bias). 2 merged: col<Vn -> masked preds (+bias), col>=Vn -> hout.
// S>1: split-K partials to g_part.
#define GBK 32
#define SPAD 36

template<int BM, int BN, int WMG, int WNG, int NF>
__global__ void __launch_bounds__(256) k_mma(
    const float* __restrict__ A, const float* __restrict__ B,
    float* __restrict__ C, const float* __restrict__ bias,
    int M, int N, int K, int S, int mode, int tstep,
    const int* __restrict__ actp)
{
    const int ASZf = BM * SPAD;
    const int BSZf = BN * SPAD;
    const int STGf = ASZf + BSZf;
    const int AF4 = BM / 32;
    const int BF4 = BN / 32;

    extern __shared__ float sm[];
    int tid  = threadIdx.x;
    int lane = tid & 31, wid = tid >> 5;
    int wm = wid % WMG, wn = wid / WMG;
    int n0 = blockIdx.x * BN;
    int m0 = blockIdx.y * BM;

    int act = actp ? *actp : M;
    if (m0 >= act) return;

    int Kc = K / S;
    int k0 = blockIdx.z * Kc;
    int nkt = Kc / GBK;

    const float* asrc[AF4]; uint32_t adst[AF4];
#pragma unroll
    for (int q = 0; q < AF4; ++q) {
        int f = tid + q*256;
        int r = f >> 3, kq = f & 7;
        int gr = m0 + r;
        if (gr >= M) gr = M - 1;
        asrc[q] = A + (size_t)gr * K + k0 + kq*4;
        adst[q] = (r * SPAD + kq*4) * 4;
    }
    const float* bsrc[BF4]; uint32_t bdst[BF4]; int bsz[BF4];
#pragma unroll
    for (int q = 0; q < BF4; ++q) {
        int f = tid + q*256;
        int r = f >> 3, kq = f & 7;
        int gn = n0 + r;
        bsz[q]  = (gn < N) ? 16 : 0;
        bsrc[q] = B + (size_t)(gn < N ? gn : 0) * K + k0 + kq*4;
        bdst[q] = (ASZf + r * SPAD + kq*4) * 4;
    }

    uint32_t smb = (uint32_t)__cvta_generic_to_shared(sm);

    float acc[2][NF][4];
#pragma unroll
    for (int i = 0; i < 2; ++i)
#pragma unroll
        for (int j = 0; j < NF; ++j)
#pragma unroll
            for (int v = 0; v < 4; ++v) acc[i][j][v] = 0.f;

#pragma unroll
    for (int s = 0; s < 3; ++s) {
        if (s < nkt) {
            uint32_t sb = smb + s * STGf * 4;
            int off = s * GBK;
#pragma unroll
            for (int q = 0; q < AF4; ++q)
                asm volatile("cp.async.cg.shared.global [%0], [%1], 16;"
                             :: "r"(sb + adst[q]), "l"(asrc[q] + off));
#pragma unroll
            for (int q = 0; q < BF4; ++q)
                asm volatile("cp.async.cg.shared.global [%0], [%1], 16, %2;"
                             :: "r"(sb + bdst[q]), "l"(bsrc[q] + off), "r"(bsz[q]));
        }
        asm volatile("cp.async.commit_group;");
    }

    int rA = lane >> 2, cA = lane & 3;
    for (int kt = 0; kt < nkt; ++kt) {
        asm volatile("cp.async.wait_group 2;");
        __syncthreads();
        {
            int s = kt + 3;
            if (s < nkt) {
                uint32_t sb = smb + (s & 3) * STGf * 4;
                int off = s * GBK;
#pragma unroll
                for (int q = 0; q < AF4; ++q)
                    asm volatile("cp.async.cg.shared.global [%0], [%1], 16;"
                                 :: "r"(sb + adst[q]), "l"(asrc[q] + off));
#pragma unroll
                for (int q = 0; q < BF4; ++q)
                    asm volatile("cp.async.cg.shared.global [%0], [%1], 16, %2;"
                                 :: "r"(sb + bdst[q]), "l"(bsrc[q] + off), "r"(bsz[q]));
            }
            asm volatile("cp.async.commit_group;");
        }
        const float* Ab = sm + (kt & 3) * STGf;
        const float* Bb = Ab + ASZf;
#pragma unroll
        for (int ka = 0; ka < 4; ++ka) {
            int kk = ka * 8;
            uint32_t a[2][4], b[NF][2];
#pragma unroll
            for (int ma = 0; ma < 2; ++ma) {
                int mb = wm*32 + ma*16;
                a[ma][0] = __float_as_uint(Ab[(mb + rA    )*SPAD + kk + cA    ]);
                a[ma][1] = __float_as_uint(Ab[(mb + rA + 8)*SPAD + kk + cA    ]);
                a[ma][2] = __float_as_uint(Ab[(mb + rA    )*SPAD + kk + cA + 4]);
                a[ma][3] = __float_as_uint(Ab[(mb + rA + 8)*SPAD + kk + cA + 4]);
            }
#pragma unroll
            for (int na = 0; na < NF; ++na) {
                int nb2 = wn*(NF*8) + na*8;
                b[na][0] = __float_as_uint(Bb[(nb2 + rA)*SPAD + kk + cA    ]);
                b[na][1] = __float_as_uint(Bb[(nb2 + rA)*SPAD + kk + cA + 4]);
            }
#pragma unroll
            for (int ma = 0; ma < 2; ++ma)
#pragma unroll
                for (int na = 0; na < NF; ++na)
                    asm volatile(
                        "mma.sync.aligned.m16n8k8.row.col.f32.tf32.tf32.f32 "
                        "{%0,%1,%2,%3},{%4,%5,%6,%7},{%8,%9},{%0,%1,%2,%3};"
                        : "+f"(acc[ma][na][0]), "+f"(acc[ma][na][1]),
                          "+f"(acc[ma][na][2]), "+f"(acc[ma][na][3])
                        : "r"(a[ma][0]), "r"(a[ma][1]), "r"(a[ma][2]), "r"(a[ma][3]),
                          "r"(b[na][0]), "r"(b[na][1]));
        }
    }

    int c2 = (lane & 3) * 2;
    float* hout = g_scratch + S_HOUT;
#pragma unroll
    for (int ma = 0; ma < 2; ++ma) {
#pragma unroll
        for (int na = 0; na < NF; ++na) {
            int row = m0 + wm*32 + ma*16 + rA;
            int col = n0 + wn*(NF*8) + na*8 + c2;
#pragma unroll
            for (int v = 0; v < 4; ++v) {
                int rr = row + (v >> 1) * 8;
                int cc = col + (v & 1);
                if (cc >= N || rr >= M) continue;
                float val = acc[ma][na][v];
                if (S > 1) {
                    g_part[(size_t)blockIdx.z * M * N + (size_t)rr * N + cc] = val;
                } else if (mode == 2) {
                    if (cc < Vn) {
                        if (tstep < g_lendec[rr])
                            C[((size_t)rr * TMn + tstep) * Vn + cc] = val + bias[cc];
                    } else {
                        hout[(size_t)rr * 4608 + (cc - Vn)] = val;
                    }
                } else {
                    if (bias) val += bias[cc];
                    C[(size_t)rr * N + cc] = val;
                }
            }
        }
    }
}

// config L (loop): BM=64 BN=128, warps 2x4, warp tile 32x32
#define LBM 64
#define LBN 128
#define LSMEM ((LBM+LBN)*SPAD*4*4)      // 110592
// config G (big): BM=128 BN=128, warps 4x2, warp tile 32x64
#define GBM2 128
#define GBN2 128
#define GSMEM ((GBM2+GBN2)*SPAD*4*4)    // 147456

// ---------------- split-K reduce for init h,c (h stored tf32-rounded) -------------
__global__ void k_inithc(const float* __restrict__ bih_, const float* __restrict__ bic)
{
    int i = blockIdx.x*256 + threadIdx.x;
    int row = i >> 10, col = i & 1023;
    float v = g_part[i] + g_part[131072 + i] + g_part[262144 + i] + g_part[393216 + i];
    if (col < 512) g_scratch[S_H + (size_t)row*512 + col]       = rndtf(v + bih_[col]);
    else           g_scratch[S_C + (size_t)row*512 + col - 512] = v + bic[col - 512];
}

// ---------------- fused attention + weighted context + x1 (512 threads/row) -------
__global__ void __launch_bounds__(512) k_attnwx(
    const float* __restrict__ attenc, const float* __restrict__ bda,
    const float* __restrict__ Watt, const float* __restrict__ enc,
    const float* __restrict__ emb, const float* __restrict__ bfb,
    float* __restrict__ outA, int t)
{
    int b = blockIdx.x;
    if (!(t < g_lendec[b])) return;
    int tid = threadIdx.x, lane = tid & 31, warp = tid >> 5;
    __shared__ __align__(16) float sd[512], sw[512], se[Pn], sa[Pn];
    __shared__ float sred[16];
    __shared__ float smax, ssum;

    const float* hb = g_scratch + S_HOUT + (size_t)b * 4608;
    sd[tid] = hb[tid] + bda[tid];
    sw[tid] = Watt[tid];
    __syncthreads();

    // scores (float4 vectorized)
    for (int p = warp; p < Pn; p += 16) {
        const float4* ae = (const float4*)(attenc + ((size_t)b * Pn + p) * 512);
        const float4* d4 = (const float4*)sd;
        const float4* w4 = (const float4*)sw;
        float s = 0.f;
#pragma unroll
        for (int j = lane; j < 128; j += 32) {
            float4 av = ae[j], dv = d4[j], wv = w4[j];
            s = fmaf(fmaxf(av.x + dv.x, 0.f), wv.x, s);
            s = fmaf(fmaxf(av.y + dv.y, 0.f), wv.y, s);
            s = fmaf(fmaxf(av.z + dv.z, 0.f), wv.z, s);
            s = fmaf(fmaxf(av.w + dv.w, 0.f), wv.w, s);
        }
        for (int o = 16; o; o >>= 1) s += __shfl_xor_sync(0xffffffffu, s, o);
        if (!lane) se[p] = s;
    }
    __syncthreads();

    float v = (tid < Pn) ? se[tid] : -3.0e38f;
    for (int o = 16; o; o >>= 1) v = fmaxf(v, __shfl_xor_sync(0xffffffffu, v, o));
    if (!lane) sred[warp] = v;
    __syncthreads();
    if (tid == 0) {
        float m = sred[0];
        for (int i = 1; i < 16; ++i) m = fmaxf(m, sred[i]);
        smax = m;
    }
    __syncthreads();
    float e = (tid < Pn) ? expf(se[tid] - smax) : 0.f;
    float s2 = e;
    for (int o = 16; o; o >>= 1) s2 += __shfl_xor_sync(0xffffffffu, s2, o);
    if (!lane) sred[warp] = s2;
    __syncthreads();
    if (tid == 0) {
        float s = 0.f;
        for (int i = 0; i < 16; ++i) s += sred[i];
        ssum = s;
    }
    __syncthreads();
    if (tid < Pn) {
        float a = e / ssum;
        sa[tid] = a;
        outA[((size_t)b * TMn + t) * Pn + tid] = a;
    }
    __syncthreads();

    // weighted context * gate -> x1[512..2560) (stored tf32-rounded)
    int ob = g_order[b];
    const float4* ep = (const float4*)(enc + (size_t)ob * Pn * ENCn) + tid;
    float4 s = make_float4(0.f, 0.f, 0.f, 0.f);
#pragma unroll 4
    for (int p = 0; p < Pn; ++p) {
        float4 ev = ep[(size_t)p * (ENCn/4)];
        float av = sa[p];
        s.x = fmaf(ev.x, av, s.x); s.y = fmaf(ev.y, av, s.y);
        s.z = fmaf(ev.z, av, s.z); s.w = fmaf(ev.w, av, s.w);
    }
    float* x1 = g_scratch + S_X1 + (size_t)b * 2560;
    float4 gp = *(const float4*)(hb + 512 + tid*4);
    float4 bb = ((const float4*)bfb)[tid];
    float4 r;
    r.x = rndtf(s.x * sigf(gp.x + bb.x)); r.y = rndtf(s.y * sigf(gp.y + bb.y));
    r.z = rndtf(s.z * sigf(gp.z + bb.z)); r.w = rndtf(s.w * sigf(gp.w + bb.w));
    ((float4*)(x1 + 512))[tid] = r;

    // embedding chunk (rounded)
    if (tid < 128) {
        int cap = g_caps[b * Tn + t];
        float4 ev = ((const float4*)(emb + (size_t)cap * 512))[tid];
        ev.x = rndtf(ev.x); ev.y = rndtf(ev.y); ev.z = rndtf(ev.z); ev.w = rndtf(ev.w);
        ((float4*)x1)[tid] = ev;
    }
}

// ---------------- LSTM: reduce 4 split-K partials + biases + hh; h stored rounded --
__global__ void k_lstm(const float* __restrict__ bih, const float* __restrict__ bhh, int t)
{
    int b = blockIdx.x;
    if (!(t < g_lendec[b])) return;
    int j = threadIdx.x;
    float g[4];
#pragma unroll
    for (int q = 0; q < 4; ++q) {
        int col = q * 512 + j;
        size_t idx = (size_t)b * 2048 + col;
        float v = g_part[idx] + g_part[262144 + idx] + g_part[524288 + idx] + g_part[786432 + idx];
        v += bih[col] + bhh[col] + g_scratch[S_HOUT + (size_t)b*4608 + 2560 + col];
        g[q] = v;
    }
    float* h = g_scratch + S_H + (size_t)b * 512;
    float* c = g_scratch + S_C + (size_t)b * 512;
    float cn = sigf(g[1]) * c[j] + sigf(g[0]) * tanhf(g[2]);
    float hn = sigf(g[3]) * tanhf(cn);
    c[j] = cn;
    h[j] = rndtf(hn);
}

// ---------------- host ----------------
static inline void gemmL(const float* A, const float* B, float* C, const float* bias,
                         int M, int N, int K, int S, int mode, int t,
                         const int* actp)
{
    dim3 g((N + LBN - 1) / LBN, (M + LBM - 1) / LBM, S);
    k_mma<LBM, LBN, 2, 4, 4><<<g, 256, LSMEM>>>(A, B, C, bias, M, N, K, S, mode, t, actp);
}
static inline void gemmG(const float* A, const float* B, float* C, const float* bias,
                         int M, int N, int K)
{
    dim3 g((N + GBN2 - 1) / GBN2, (M + GBM2 - 1) / GBM2, 1);
    k_mma<GBM2, GBN2, 4, 2, 8><<<g, 256, GSMEM>>>(A, B, C, bias, M, N, K, 1, 0, 0, nullptr);
}

extern "C" void kernel_launch(void* const* d_in, const int* in_sizes, int n_in,
                              void* d_out, int out_size)
{
    const float* enc  = (const float*)d_in[0];
    const int*   caps = (const int*)  d_in[1];
    const int*   lenc = (const int*)  d_in[2];
    const float* emb  = (const float*)d_in[3];
    const float* bea = (const float*)d_in[5];
    const float* bda = (const float*)d_in[7];
    const float* Wat = (const float*)d_in[8];
    const float* bih_= (const float*)d_in[11];
    const float* bic = (const float*)d_in[13];
    const float* bih = (const float*)d_in[15];
    const float* bhh = (const float*)d_in[17];
    const float* bfb = (const float*)d_in[19];
    const float* bfc = (const float*)d_in[21];
    float* out = (float*)d_out;

    cudaFuncSetAttribute((const void*)k_mma<LBM, LBN, 2, 4, 4>,
                         cudaFuncAttributeMaxDynamicSharedMemorySize, LSMEM);
    cudaFuncSetAttribute((const void*)k_mma<GBM2, GBN2, 4, 2, 8>,
                         cudaFuncAttributeMaxDynamicSharedMemorySize, GSMEM);

    float* S0 = nullptr;
    cudaGetSymbolAddress((void**)&S0, g_scratch);
    int* actd = nullptr;
    cudaGetSymbolAddress((void**)&actd, g_act);
    float* attenc = S0 + S_ATTENC;
    float* mu     = S0 + S_MU;
    float* h      = S0 + S_H;
    float* x1     = S0 + S_X1;
    float* hout   = S0 + S_HOUT;
    float* wbig   = S0 + S_WBIG;
    float* wcombo = S0 + S_WBIG + (size_t)Vn * 512;
    float* winit  = S0 + S_WINIT;
    float* wih    = S0 + S_WIH;
    float* wea    = S0 + S_WEA;
    float* encr   = S0 + S_ENCR;

    // init
    k_sort<<<1, 128>>>(lenc, caps, out);
    k_zero<<<592, 256>>>(out);
    k_pack<<<2048, 256>>>((const float*)d_in[20], (const float*)d_in[6],
                          (const float*)d_in[18], (const float*)d_in[16],
                          (const float*)d_in[10], (const float*)d_in[12],
                          (const float*)d_in[14], (const float*)d_in[4]);
    // fused: mu (rounded) + gathered tf32-rounded enc copy
    k_mucopy<<<dim3(4, 128), 128>>>(enc, mu, encr);
    // h,c init (all operands pre-rounded)
    gemmL(mu, winit, nullptr, nullptr, 128, 1024, 2048, 4, 0, 0, nullptr);
    k_inithc<<<512, 256>>>(bih_, bic);
    // att_enc precompute: CVT-free, gather-free (encr is sorted + rounded)
    gemmG(encr, wea, attenc, bea, Bn * Pn, 512, 2048);
    // prologue hout for t=0 (h pre-rounded, wcombo pre-rounded)
    gemmL(h, wcombo, hout, nullptr, 128, 4608, 512, 1, 0, 0, nullptr);

    // decode loop: attnwx -> gates -> lstm -> merged(fc_t + hout_{t+1})
    for (int t = 0; t < TMn; ++t) {
        const int* ap = actd + t;
        k_attnwx<<<128, 512>>>(attenc, bda, Wat, enc, emb, bfb, out + OFF_ALPHA, t);
        gemmL(x1, wih, nullptr, nullptr, 128, 2048, 2560, 4, 0, 0, ap);
        k_lstm<<<128, 512>>>(bih, bhh, t);
        gemmL(h, wbig, out + OFF_PRED, bfc, 128, Vn + 4608, 512, 1, 2, t, ap);
    }
}